// round 12
// baseline (speedup 1.0000x reference)
#include <cuda_runtime.h>
#include <math.h>
#include <stdint.h>

// Flow_49546742727298: CNF Euler, exact divergence via analytic trace.
// R12: R11 persistent-warp tf32-MMA + hot-loop instruction cut:
//   - permuted smem h-buffer: A-frag loads become 8x LDS.128 (was 32x LDS.32
//     + separate cvt); h stored pre-converted to tf32. Conflict-free both ways.
//   - c_j hoisted to per-tile registers; step-dependent bias as flat rows.

#define THREADS 128        // 4 warps per CTA
#define NSTEPS  2
#define GRID    (3 * 148)  // 3 CTAs/SM * 148 SMs (regfile-exact)

__device__ __forceinline__ uint32_t tf32(float f) {
    uint32_t r; asm("cvt.rna.tf32.f32 %0, %1;" : "=r"(r) : "f"(f)); return r;
}
__device__ __forceinline__ float fast_tanh(float x) {
    float y; asm("tanh.approx.f32 %0, %1;" : "=f"(y) : "f"(x)); return y;
}
__device__ __forceinline__ void mma_tf32(float c[4], const uint32_t a[4],
                                         const uint32_t b0, const uint32_t b1) {
    asm("mma.sync.aligned.m16n8k8.row.col.f32.tf32.tf32.f32 "
        "{%0,%1,%2,%3}, {%4,%5,%6,%7}, {%8,%9}, {%0,%1,%2,%3};"
        : "+f"(c[0]), "+f"(c[1]), "+f"(c[2]), "+f"(c[3])
        : "r"(a[0]), "r"(a[1]), "r"(a[2]), "r"(a[3]), "r"(b0), "r"(b1));
}

__global__ void __launch_bounds__(THREADS, 3)
flow_kernel(const float* __restrict__ x0,
            const float* __restrict__ W1,
            const float* __restrict__ b1,
            const float* __restrict__ W2,
            const float* __restrict__ b2,
            float* __restrict__ out,
            int batch)
{
    // Permuted h buffer: word addr(r,c) =
    //   (c>>3)*128 + (c&3)*32 + (r&7)*4 + ((c>>2)&1)*2 + (r>>3)
    __shared__ __align__(16) uint32_t hbuf[4][1024];
    __shared__ float sbias[2][64];   // [s][j]: b1[j] + t_s * wt[j]
    __shared__ float scj[64];        // c_j
    __shared__ __align__(8) float sb2s[16];

    const int tid  = threadIdx.x;
    const int lane = tid & 31;
    const int warp = tid >> 5;
    const int g    = lane >> 2;   // row-within-8
    const int tg   = lane & 3;    // thread-in-group
    const int gb   = lane & ~3;   // group base lane

    // ---- per-CTA tables ----
    if (tid < 64) {
        const int j = tid;
        float c = 0.f;
        #pragma unroll
        for (int i = 0; i < 16; i++)
            c += W1[i * 64 + j] * W2[j * 16 + i];
        float bb = b1[j];
        float wt = W1[16 * 64 + j];
        scj[j] = c;
        sbias[0][j] = bb;
        sbias[1][j] = fmaf(0.5f, wt, bb);
    } else if (tid < 80) {
        sb2s[tid - 64] = b2[tid - 64];
    }
    __syncthreads();

    // csum via warp reduce (all lanes)
    float csum;
    {
        float cpart = scj[lane] + scj[lane + 32];
        #pragma unroll
        for (int d = 16; d >= 1; d >>= 1)
            cpart += __shfl_xor_sync(0xffffffffu, cpart, d);
        csum = cpart;
    }

    // c_j at this thread's C columns (2tg, 2tg+1) per nt — loop-invariant regs
    float cja[8], cjb[8];
    #pragma unroll
    for (int nt = 0; nt < 8; nt++) {
        float2 cc = *(const float2*)&scj[8 * nt + 2 * tg];
        cja[nt] = cc.x; cjb[nt] = cc.y;
    }

    // ---- persistent weight fragments ----
    uint32_t w1f[8][2][2];
    #pragma unroll
    for (int nt = 0; nt < 8; nt++)
        #pragma unroll
        for (int kt = 0; kt < 2; kt++) {
            w1f[nt][kt][0] = tf32(W1[(8 * kt + tg)     * 64 + 8 * nt + g]);
            w1f[nt][kt][1] = tf32(W1[(8 * kt + tg + 4) * 64 + 8 * nt + g]);
        }
    uint32_t w2f[8][2][2];
    #pragma unroll
    for (int kt = 0; kt < 8; kt++)
        #pragma unroll
        for (int nt = 0; nt < 2; nt++) {
            w2f[kt][nt][0] = tf32(W2[(8 * kt + tg)     * 16 + 8 * nt + g]);
            w2f[kt][nt][1] = tf32(W2[(8 * kt + tg + 4) * 16 + 8 * nt + g]);
        }

    uint32_t* buf = hbuf[warp];
    const float dt = 0.5f;

    // h-store word addresses (o = 0,1), loop-invariant:
    //   c = 8nt + 2tg + o -> nt*128 + (c&3)*32 + g*4 + ((c>>2)&1)*2
    int stA, stB;
    {
        int c0 = 2 * tg;       // o = 0
        int c1 = 2 * tg + 1;   // o = 1
        stA = (c0 & 3) * 32 + g * 4 + ((c0 >> 2) & 1) * 2;
        stB = (c1 & 3) * 32 + g * 4 + ((c1 >> 2) & 1) * 2;
    }
    // A-frag load base: kt*128 + tg*32 + g*4
    const int ldb = tg * 32 + g * 4;

    const int gwarp  = blockIdx.x * 4 + warp;
    const int nwarps = GRID * 4;
    const int ntiles = batch >> 4;

    for (int wt = gwarp; wt < ntiles; wt += nwarps) {
        const int row0 = wt << 4;

        float xe[2][4];
        #pragma unroll
        for (int kt = 0; kt < 2; kt++) {
            xe[kt][0] = x0[(size_t)(row0 + g)     * 16 + 8 * kt + tg];
            xe[kt][1] = x0[(size_t)(row0 + g + 8) * 16 + 8 * kt + tg];
            xe[kt][2] = x0[(size_t)(row0 + g)     * 16 + 8 * kt + tg + 4];
            xe[kt][3] = x0[(size_t)(row0 + g + 8) * 16 + 8 * kt + tg + 4];
        }

        float logq0 = 0.f, logq1 = 0.f;

        #pragma unroll
        for (int s = 0; s < NSTEPS; s++) {
            uint32_t xa[2][4];
            #pragma unroll
            for (int kt = 0; kt < 2; kt++)
                #pragma unroll
                for (int i = 0; i < 4; i++)
                    xa[kt][i] = tf32(xe[kt][i]);

            // GEMM1: h_pre = x @ W1 + bse (bias from per-step row)
            float h[8][4];
            #pragma unroll
            for (int nt = 0; nt < 8; nt++) {
                float2 bb = *(const float2*)&sbias[s][8 * nt + 2 * tg];
                h[nt][0] = bb.x; h[nt][1] = bb.y;
                h[nt][2] = bb.x; h[nt][3] = bb.y;
                mma_tf32(h[nt], xa[0], w1f[nt][0][0], w1f[nt][0][1]);
                mma_tf32(h[nt], xa[1], w1f[nt][1][0], w1f[nt][1][1]);
            }

            // tanh + divergence partials; store tf32 h into permuted buffer
            float d0 = 0.f, d1 = 0.f;
            #pragma unroll
            for (int nt = 0; nt < 8; nt++) {
                h[nt][0] = fast_tanh(h[nt][0]);
                h[nt][1] = fast_tanh(h[nt][1]);
                h[nt][2] = fast_tanh(h[nt][2]);
                h[nt][3] = fast_tanh(h[nt][3]);
                d0 = fmaf(h[nt][0] * h[nt][0], cja[nt], d0);
                d0 = fmaf(h[nt][1] * h[nt][1], cjb[nt], d0);
                d1 = fmaf(h[nt][2] * h[nt][2], cja[nt], d1);
                d1 = fmaf(h[nt][3] * h[nt][3], cjb[nt], d1);
                uint2 pa = make_uint2(tf32(h[nt][0]), tf32(h[nt][2])); // (r=g, r=g+8) col 2tg
                uint2 pb = make_uint2(tf32(h[nt][1]), tf32(h[nt][3])); // col 2tg+1
                *(uint2*)&buf[nt * 128 + stA] = pa;
                *(uint2*)&buf[nt * 128 + stB] = pb;
            }
            d0 += __shfl_xor_sync(0xffffffffu, d0, 1);
            d0 += __shfl_xor_sync(0xffffffffu, d0, 2);
            d1 += __shfl_xor_sync(0xffffffffu, d1, 1);
            d1 += __shfl_xor_sync(0xffffffffu, d1, 2);
            logq0 -= dt * (csum - d0);
            logq1 -= dt * (csum - d1);

            __syncwarp();

            // GEMM2: v = h @ W2 + b2; A-frags arrive as single LDS.128 each
            float v[2][4];
            {
                float2 bb0 = *(const float2*)&sb2s[2 * tg];
                float2 bb1 = *(const float2*)&sb2s[8 + 2 * tg];
                float va0[4] = {bb0.x, bb0.y, bb0.x, bb0.y};
                float vb0[4] = {0.f, 0.f, 0.f, 0.f};
                float va1[4] = {bb1.x, bb1.y, bb1.x, bb1.y};
                float vb1[4] = {0.f, 0.f, 0.f, 0.f};
                #pragma unroll
                for (int kt = 0; kt < 8; kt++) {
                    uint4 hv = *(const uint4*)&buf[kt * 128 + ldb];
                    uint32_t ha[4] = {hv.x, hv.y, hv.z, hv.w};
                    if (kt < 4) {
                        mma_tf32(va0, ha, w2f[kt][0][0], w2f[kt][0][1]);
                        mma_tf32(va1, ha, w2f[kt][1][0], w2f[kt][1][1]);
                    } else {
                        mma_tf32(vb0, ha, w2f[kt][0][0], w2f[kt][0][1]);
                        mma_tf32(vb1, ha, w2f[kt][1][0], w2f[kt][1][1]);
                    }
                }
                #pragma unroll
                for (int i = 0; i < 4; i++) {
                    v[0][i] = va0[i] + vb0[i];
                    v[1][i] = va1[i] + vb1[i];
                }
            }
            __syncwarp();

            // v: C frag -> x A-layout via shuffles
            #pragma unroll
            for (int kt = 0; kt < 2; kt++) {
                int src0 = gb | (tg >> 1);
                int src1 = gb | (2 + (tg >> 1));
                float e00 = __shfl_sync(0xffffffffu, v[kt][0], src0);
                float e01 = __shfl_sync(0xffffffffu, v[kt][1], src0);
                float e10 = __shfl_sync(0xffffffffu, v[kt][2], src0);
                float e11 = __shfl_sync(0xffffffffu, v[kt][3], src0);
                float f00 = __shfl_sync(0xffffffffu, v[kt][0], src1);
                float f01 = __shfl_sync(0xffffffffu, v[kt][1], src1);
                float f10 = __shfl_sync(0xffffffffu, v[kt][2], src1);
                float f11 = __shfl_sync(0xffffffffu, v[kt][3], src1);
                bool odd = (tg & 1);
                xe[kt][0] = fmaf(dt, odd ? e01 : e00, xe[kt][0]);
                xe[kt][1] = fmaf(dt, odd ? e11 : e10, xe[kt][1]);
                xe[kt][2] = fmaf(dt, odd ? f01 : f00, xe[kt][2]);
                xe[kt][3] = fmaf(dt, odd ? f11 : f10, xe[kt][3]);
            }
        }

        // output
        #pragma unroll
        for (int kt = 0; kt < 2; kt++) {
            out[(size_t)(row0 + g)     * 16 + 8 * kt + tg]     = xe[kt][0];
            out[(size_t)(row0 + g + 8) * 16 + 8 * kt + tg]     = xe[kt][1];
            out[(size_t)(row0 + g)     * 16 + 8 * kt + tg + 4] = xe[kt][2];
            out[(size_t)(row0 + g + 8) * 16 + 8 * kt + tg + 4] = xe[kt][3];
        }
        if (tg == 0) {
            out[(size_t)batch * 16 + row0 + g]     = logq0;
            out[(size_t)batch * 16 + row0 + g + 8] = logq1;
        }
    }
}

extern "C" void kernel_launch(void* const* d_in, const int* in_sizes, int n_in,
                              void* d_out, int out_size) {
    const float* x0 = (const float*)d_in[0];
    const float* W1 = (const float*)d_in[1];
    const float* b1 = (const float*)d_in[2];
    const float* W2 = (const float*)d_in[3];
    const float* b2 = (const float*)d_in[4];
    float* out = (float*)d_out;

    const int batch = in_sizes[0] / 16;
    flow_kernel<<<GRID, THREADS>>>(x0, W1, b1, W2, b2, out, batch);
}

// round 13
// speedup vs baseline: 1.2748x; 1.2748x over previous
#include <cuda_runtime.h>
#include <math.h>
#include <stdint.h>

// Flow_49546742727298: CNF Euler, exact divergence via analytic trace.
// R13: R12's LDS.128 A-frag idea with a CORRECT conflict-free permuted layout:
//   word(r,c) = (c>>3)*128 + (r&7)*16 + ((((c&7)&3)*4) ^ swz) + ((c&7)>>2)*2 + (r>>3)
//   swz = (((r&7)>>1)&1)*4.  Loads: 8x LDS.128, all 32 banks per phase.
//   Stores: 16x STS.64, disjoint bank halves per g parity-pair. Verified.

#define THREADS 128        // 4 warps per CTA
#define NSTEPS  2
#define GRID    (3 * 148)  // 3 CTAs/SM * 148 SMs (regfile-exact)

__device__ __forceinline__ uint32_t tf32(float f) {
    uint32_t r; asm("cvt.rna.tf32.f32 %0, %1;" : "=r"(r) : "f"(f)); return r;
}
__device__ __forceinline__ float fast_tanh(float x) {
    float y; asm("tanh.approx.f32 %0, %1;" : "=f"(y) : "f"(x)); return y;
}
__device__ __forceinline__ void mma_tf32(float c[4], const uint32_t a[4],
                                         const uint32_t b0, const uint32_t b1) {
    asm("mma.sync.aligned.m16n8k8.row.col.f32.tf32.tf32.f32 "
        "{%0,%1,%2,%3}, {%4,%5,%6,%7}, {%8,%9}, {%0,%1,%2,%3};"
        : "+f"(c[0]), "+f"(c[1]), "+f"(c[2]), "+f"(c[3])
        : "r"(a[0]), "r"(a[1]), "r"(a[2]), "r"(a[3]), "r"(b0), "r"(b1));
}

__global__ void __launch_bounds__(THREADS, 3)
flow_kernel(const float* __restrict__ x0,
            const float* __restrict__ W1,
            const float* __restrict__ b1,
            const float* __restrict__ W2,
            const float* __restrict__ b2,
            float* __restrict__ out,
            int batch)
{
    __shared__ __align__(16) uint32_t hbuf[4][1024];
    __shared__ float sbias[2][64];   // [s][j]: b1[j] + t_s * wt[j]
    __shared__ float scj[64];        // c_j
    __shared__ __align__(8) float sb2s[16];

    const int tid  = threadIdx.x;
    const int lane = tid & 31;
    const int warp = tid >> 5;
    const int g    = lane >> 2;   // row-within-8
    const int tg   = lane & 3;    // thread-in-group
    const int gb   = lane & ~3;   // group base lane

    // ---- per-CTA tables ----
    if (tid < 64) {
        const int j = tid;
        float c = 0.f;
        #pragma unroll
        for (int i = 0; i < 16; i++)
            c += W1[i * 64 + j] * W2[j * 16 + i];
        float bb = b1[j];
        float wt = W1[16 * 64 + j];
        scj[j] = c;
        sbias[0][j] = bb;
        sbias[1][j] = fmaf(0.5f, wt, bb);
    } else if (tid < 80) {
        sb2s[tid - 64] = b2[tid - 64];
    }
    __syncthreads();

    // csum via warp reduce (all lanes)
    float csum;
    {
        float cpart = scj[lane] + scj[lane + 32];
        #pragma unroll
        for (int d = 16; d >= 1; d >>= 1)
            cpart += __shfl_xor_sync(0xffffffffu, cpart, d);
        csum = cpart;
    }

    // c_j at this thread's C columns (2tg, 2tg+1) per nt — loop-invariant regs
    float cja[8], cjb[8];
    #pragma unroll
    for (int nt = 0; nt < 8; nt++) {
        float2 cc = *(const float2*)&scj[8 * nt + 2 * tg];
        cja[nt] = cc.x; cjb[nt] = cc.y;
    }

    // ---- persistent weight fragments ----
    uint32_t w1f[8][2][2];
    #pragma unroll
    for (int nt = 0; nt < 8; nt++)
        #pragma unroll
        for (int kt = 0; kt < 2; kt++) {
            w1f[nt][kt][0] = tf32(W1[(8 * kt + tg)     * 64 + 8 * nt + g]);
            w1f[nt][kt][1] = tf32(W1[(8 * kt + tg + 4) * 64 + 8 * nt + g]);
        }
    uint32_t w2f[8][2][2];
    #pragma unroll
    for (int kt = 0; kt < 8; kt++)
        #pragma unroll
        for (int nt = 0; nt < 2; nt++) {
            w2f[kt][nt][0] = tf32(W2[(8 * kt + tg)     * 16 + 8 * nt + g]);
            w2f[kt][nt][1] = tf32(W2[(8 * kt + tg + 4) * 16 + 8 * nt + g]);
        }

    uint32_t* buf = hbuf[warp];
    const float dt = 0.5f;

    // Conflict-free permuted addresses (see header comment).
    const int swzg = ((g >> 1) & 1) * 4;
    int stA, stB;
    {
        int c0 = 2 * tg;       // o = 0
        int c1 = 2 * tg + 1;   // o = 1
        stA = g * 16 + (((c0 & 3) * 4) ^ swzg) + ((c0 >> 2) & 1) * 2;
        stB = g * 16 + (((c1 & 3) * 4) ^ swzg) + ((c1 >> 2) & 1) * 2;
    }
    const int ldb = g * 16 + ((tg * 4) ^ swzg);

    const int gwarp  = blockIdx.x * 4 + warp;
    const int nwarps = GRID * 4;
    const int ntiles = batch >> 4;

    for (int wt = gwarp; wt < ntiles; wt += nwarps) {
        const int row0 = wt << 4;

        float xe[2][4];
        #pragma unroll
        for (int kt = 0; kt < 2; kt++) {
            xe[kt][0] = x0[(size_t)(row0 + g)     * 16 + 8 * kt + tg];
            xe[kt][1] = x0[(size_t)(row0 + g + 8) * 16 + 8 * kt + tg];
            xe[kt][2] = x0[(size_t)(row0 + g)     * 16 + 8 * kt + tg + 4];
            xe[kt][3] = x0[(size_t)(row0 + g + 8) * 16 + 8 * kt + tg + 4];
        }

        float logq0 = 0.f, logq1 = 0.f;

        #pragma unroll
        for (int s = 0; s < NSTEPS; s++) {
            uint32_t xa[2][4];
            #pragma unroll
            for (int kt = 0; kt < 2; kt++)
                #pragma unroll
                for (int i = 0; i < 4; i++)
                    xa[kt][i] = tf32(xe[kt][i]);

            // GEMM1: h_pre = x @ W1 + bse
            float h[8][4];
            #pragma unroll
            for (int nt = 0; nt < 8; nt++) {
                float2 bb = *(const float2*)&sbias[s][8 * nt + 2 * tg];
                h[nt][0] = bb.x; h[nt][1] = bb.y;
                h[nt][2] = bb.x; h[nt][3] = bb.y;
                mma_tf32(h[nt], xa[0], w1f[nt][0][0], w1f[nt][0][1]);
                mma_tf32(h[nt], xa[1], w1f[nt][1][0], w1f[nt][1][1]);
            }

            // tanh + divergence partials; store tf32 h (permuted, conflict-free)
            float d0 = 0.f, d1 = 0.f;
            #pragma unroll
            for (int nt = 0; nt < 8; nt++) {
                h[nt][0] = fast_tanh(h[nt][0]);
                h[nt][1] = fast_tanh(h[nt][1]);
                h[nt][2] = fast_tanh(h[nt][2]);
                h[nt][3] = fast_tanh(h[nt][3]);
                d0 = fmaf(h[nt][0] * h[nt][0], cja[nt], d0);
                d0 = fmaf(h[nt][1] * h[nt][1], cjb[nt], d0);
                d1 = fmaf(h[nt][2] * h[nt][2], cja[nt], d1);
                d1 = fmaf(h[nt][3] * h[nt][3], cjb[nt], d1);
                uint2 pa = make_uint2(tf32(h[nt][0]), tf32(h[nt][2])); // col 2tg:   rows g, g+8
                uint2 pb = make_uint2(tf32(h[nt][1]), tf32(h[nt][3])); // col 2tg+1: rows g, g+8
                *(uint2*)&buf[nt * 128 + stA] = pa;
                *(uint2*)&buf[nt * 128 + stB] = pb;
            }
            d0 += __shfl_xor_sync(0xffffffffu, d0, 1);
            d0 += __shfl_xor_sync(0xffffffffu, d0, 2);
            d1 += __shfl_xor_sync(0xffffffffu, d1, 1);
            d1 += __shfl_xor_sync(0xffffffffu, d1, 2);
            logq0 -= dt * (csum - d0);
            logq1 -= dt * (csum - d1);

            __syncwarp();

            // GEMM2: v = h @ W2 + b2; each A-frag is a single LDS.128
            float v[2][4];
            {
                float2 bb0 = *(const float2*)&sb2s[2 * tg];
                float2 bb1 = *(const float2*)&sb2s[8 + 2 * tg];
                float va0[4] = {bb0.x, bb0.y, bb0.x, bb0.y};
                float vb0[4] = {0.f, 0.f, 0.f, 0.f};
                float va1[4] = {bb1.x, bb1.y, bb1.x, bb1.y};
                float vb1[4] = {0.f, 0.f, 0.f, 0.f};
                #pragma unroll
                for (int kt = 0; kt < 8; kt++) {
                    uint4 hv = *(const uint4*)&buf[kt * 128 + ldb];
                    uint32_t ha[4] = {hv.x, hv.y, hv.z, hv.w};
                    if (kt < 4) {
                        mma_tf32(va0, ha, w2f[kt][0][0], w2f[kt][0][1]);
                        mma_tf32(va1, ha, w2f[kt][1][0], w2f[kt][1][1]);
                    } else {
                        mma_tf32(vb0, ha, w2f[kt][0][0], w2f[kt][0][1]);
                        mma_tf32(vb1, ha, w2f[kt][1][0], w2f[kt][1][1]);
                    }
                }
                #pragma unroll
                for (int i = 0; i < 4; i++) {
                    v[0][i] = va0[i] + vb0[i];
                    v[1][i] = va1[i] + vb1[i];
                }
            }
            __syncwarp();

            // v: C frag -> x A-layout via shuffles
            #pragma unroll
            for (int kt = 0; kt < 2; kt++) {
                int src0 = gb | (tg >> 1);
                int src1 = gb | (2 + (tg >> 1));
                float e00 = __shfl_sync(0xffffffffu, v[kt][0], src0);
                float e01 = __shfl_sync(0xffffffffu, v[kt][1], src0);
                float e10 = __shfl_sync(0xffffffffu, v[kt][2], src0);
                float e11 = __shfl_sync(0xffffffffu, v[kt][3], src0);
                float f00 = __shfl_sync(0xffffffffu, v[kt][0], src1);
                float f01 = __shfl_sync(0xffffffffu, v[kt][1], src1);
                float f10 = __shfl_sync(0xffffffffu, v[kt][2], src1);
                float f11 = __shfl_sync(0xffffffffu, v[kt][3], src1);
                bool odd = (tg & 1);
                xe[kt][0] = fmaf(dt, odd ? e01 : e00, xe[kt][0]);
                xe[kt][1] = fmaf(dt, odd ? e11 : e10, xe[kt][1]);
                xe[kt][2] = fmaf(dt, odd ? f01 : f00, xe[kt][2]);
                xe[kt][3] = fmaf(dt, odd ? f11 : f10, xe[kt][3]);
            }
        }

        // output
        #pragma unroll
        for (int kt = 0; kt < 2; kt++) {
            out[(size_t)(row0 + g)     * 16 + 8 * kt + tg]     = xe[kt][0];
            out[(size_t)(row0 + g + 8) * 16 + 8 * kt + tg]     = xe[kt][1];
            out[(size_t)(row0 + g)     * 16 + 8 * kt + tg + 4] = xe[kt][2];
            out[(size_t)(row0 + g + 8) * 16 + 8 * kt + tg + 4] = xe[kt][3];
        }
        if (tg == 0) {
            out[(size_t)batch * 16 + row0 + g]     = logq0;
            out[(size_t)batch * 16 + row0 + g + 8] = logq1;
        }
    }
}

extern "C" void kernel_launch(void* const* d_in, const int* in_sizes, int n_in,
                              void* d_out, int out_size) {
    const float* x0 = (const float*)d_in[0];
    const float* W1 = (const float*)d_in[1];
    const float* b1 = (const float*)d_in[2];
    const float* W2 = (const float*)d_in[3];
    const float* b2 = (const float*)d_in[4];
    float* out = (float*)d_out;

    const int batch = in_sizes[0] / 16;
    flow_kernel<<<GRID, THREADS>>>(x0, W1, b1, W2, b2, out, batch);
}

// round 14
// speedup vs baseline: 1.2808x; 1.0047x over previous
#include <cuda_runtime.h>
#include <math.h>
#include <stdint.h>

// Flow_49546742727298: CNF Euler, exact divergence via analytic trace.
// R14: R13 + two independent 16-sample tiles per warp (ILP over occupancy):
//      launch_bounds(128,2) -> 256-reg budget, 2 CTAs/SM, each warp interleaves
//      two full tile pipelines (4 independent chains per SMSP vs 3 in R13).

#define THREADS 128        // 4 warps per CTA
#define NSTEPS  2
#define NCTA    2
#define GRID    (NCTA * 148)
#define TPW     2          // tiles per warp, in flight

__device__ __forceinline__ uint32_t tf32(float f) {
    uint32_t r; asm("cvt.rna.tf32.f32 %0, %1;" : "=r"(r) : "f"(f)); return r;
}
__device__ __forceinline__ float fast_tanh(float x) {
    float y; asm("tanh.approx.f32 %0, %1;" : "=f"(y) : "f"(x)); return y;
}
__device__ __forceinline__ void mma_tf32(float c[4], const uint32_t a[4],
                                         const uint32_t b0, const uint32_t b1) {
    asm("mma.sync.aligned.m16n8k8.row.col.f32.tf32.tf32.f32 "
        "{%0,%1,%2,%3}, {%4,%5,%6,%7}, {%8,%9}, {%0,%1,%2,%3};"
        : "+f"(c[0]), "+f"(c[1]), "+f"(c[2]), "+f"(c[3])
        : "r"(a[0]), "r"(a[1]), "r"(a[2]), "r"(a[3]), "r"(b0), "r"(b1));
}

__global__ void __launch_bounds__(THREADS, NCTA)
flow_kernel(const float* __restrict__ x0,
            const float* __restrict__ W1,
            const float* __restrict__ b1,
            const float* __restrict__ W2,
            const float* __restrict__ b2,
            float* __restrict__ out,
            int batch)
{
    // Permuted h buffers (R13 layout, conflict-free), one per (warp, tile-slot).
    __shared__ __align__(16) uint32_t hbuf[4 * TPW][1024];
    __shared__ float sbias[2][64];
    __shared__ float scj[64];
    __shared__ __align__(8) float sb2s[16];

    const int tid  = threadIdx.x;
    const int lane = tid & 31;
    const int warp = tid >> 5;
    const int g    = lane >> 2;
    const int tg   = lane & 3;
    const int gb   = lane & ~3;

    if (tid < 64) {
        const int j = tid;
        float c = 0.f;
        #pragma unroll
        for (int i = 0; i < 16; i++)
            c += W1[i * 64 + j] * W2[j * 16 + i];
        float bb = b1[j];
        float wt = W1[16 * 64 + j];
        scj[j] = c;
        sbias[0][j] = bb;
        sbias[1][j] = fmaf(0.5f, wt, bb);
    } else if (tid < 80) {
        sb2s[tid - 64] = b2[tid - 64];
    }
    __syncthreads();

    float csum;
    {
        float cpart = scj[lane] + scj[lane + 32];
        #pragma unroll
        for (int d = 16; d >= 1; d >>= 1)
            cpart += __shfl_xor_sync(0xffffffffu, cpart, d);
        csum = cpart;
    }

    float cja[8], cjb[8];
    #pragma unroll
    for (int nt = 0; nt < 8; nt++) {
        float2 cc = *(const float2*)&scj[8 * nt + 2 * tg];
        cja[nt] = cc.x; cjb[nt] = cc.y;
    }

    uint32_t w1f[8][2][2];
    #pragma unroll
    for (int nt = 0; nt < 8; nt++)
        #pragma unroll
        for (int kt = 0; kt < 2; kt++) {
            w1f[nt][kt][0] = tf32(W1[(8 * kt + tg)     * 64 + 8 * nt + g]);
            w1f[nt][kt][1] = tf32(W1[(8 * kt + tg + 4) * 64 + 8 * nt + g]);
        }
    uint32_t w2f[8][2][2];
    #pragma unroll
    for (int kt = 0; kt < 8; kt++)
        #pragma unroll
        for (int nt = 0; nt < 2; nt++) {
            w2f[kt][nt][0] = tf32(W2[(8 * kt + tg)     * 16 + 8 * nt + g]);
            w2f[kt][nt][1] = tf32(W2[(8 * kt + tg + 4) * 16 + 8 * nt + g]);
        }

    uint32_t* buf[TPW];
    #pragma unroll
    for (int u = 0; u < TPW; u++) buf[u] = hbuf[warp * TPW + u];
    const float dt = 0.5f;

    const int swzg = ((g >> 1) & 1) * 4;
    int stA, stB;
    {
        int c0 = 2 * tg, c1 = 2 * tg + 1;
        stA = g * 16 + (((c0 & 3) * 4) ^ swzg) + ((c0 >> 2) & 1) * 2;
        stB = g * 16 + (((c1 & 3) * 4) ^ swzg) + ((c1 >> 2) & 1) * 2;
    }
    const int ldb = g * 16 + ((tg * 4) ^ swzg);

    const int gwarp  = blockIdx.x * 4 + warp;
    const int nwarps = GRID * 4;
    const int npairs = batch >> 5;           // 2 tiles of 16 per iteration

    for (int wp = gwarp; wp < npairs; wp += nwarps) {
        int row0[TPW];
        row0[0] = (wp * 2) << 4;
        row0[1] = row0[0] + 16;

        float xe[TPW][2][4];
        #pragma unroll
        for (int u = 0; u < TPW; u++)
            #pragma unroll
            for (int kt = 0; kt < 2; kt++) {
                xe[u][kt][0] = x0[(size_t)(row0[u] + g)     * 16 + 8 * kt + tg];
                xe[u][kt][1] = x0[(size_t)(row0[u] + g + 8) * 16 + 8 * kt + tg];
                xe[u][kt][2] = x0[(size_t)(row0[u] + g)     * 16 + 8 * kt + tg + 4];
                xe[u][kt][3] = x0[(size_t)(row0[u] + g + 8) * 16 + 8 * kt + tg + 4];
            }

        float logq0[TPW] = {0.f, 0.f}, logq1[TPW] = {0.f, 0.f};

        #pragma unroll
        for (int s = 0; s < NSTEPS; s++) {
            // GEMM1 for both tiles, interleaved
            float h[TPW][8][4];
            #pragma unroll
            for (int u = 0; u < TPW; u++) {
                uint32_t xa[2][4];
                #pragma unroll
                for (int kt = 0; kt < 2; kt++)
                    #pragma unroll
                    for (int i = 0; i < 4; i++)
                        xa[kt][i] = tf32(xe[u][kt][i]);
                #pragma unroll
                for (int nt = 0; nt < 8; nt++) {
                    float2 bb = *(const float2*)&sbias[s][8 * nt + 2 * tg];
                    h[u][nt][0] = bb.x; h[u][nt][1] = bb.y;
                    h[u][nt][2] = bb.x; h[u][nt][3] = bb.y;
                    mma_tf32(h[u][nt], xa[0], w1f[nt][0][0], w1f[nt][0][1]);
                    mma_tf32(h[u][nt], xa[1], w1f[nt][1][0], w1f[nt][1][1]);
                }
            }

            // tanh + div partials + permuted store, both tiles
            float d0[TPW], d1[TPW];
            #pragma unroll
            for (int u = 0; u < TPW; u++) {
                d0[u] = 0.f; d1[u] = 0.f;
                #pragma unroll
                for (int nt = 0; nt < 8; nt++) {
                    h[u][nt][0] = fast_tanh(h[u][nt][0]);
                    h[u][nt][1] = fast_tanh(h[u][nt][1]);
                    h[u][nt][2] = fast_tanh(h[u][nt][2]);
                    h[u][nt][3] = fast_tanh(h[u][nt][3]);
                    d0[u] = fmaf(h[u][nt][0] * h[u][nt][0], cja[nt], d0[u]);
                    d0[u] = fmaf(h[u][nt][1] * h[u][nt][1], cjb[nt], d0[u]);
                    d1[u] = fmaf(h[u][nt][2] * h[u][nt][2], cja[nt], d1[u]);
                    d1[u] = fmaf(h[u][nt][3] * h[u][nt][3], cjb[nt], d1[u]);
                    uint2 pa = make_uint2(tf32(h[u][nt][0]), tf32(h[u][nt][2]));
                    uint2 pb = make_uint2(tf32(h[u][nt][1]), tf32(h[u][nt][3]));
                    *(uint2*)&buf[u][nt * 128 + stA] = pa;
                    *(uint2*)&buf[u][nt * 128 + stB] = pb;
                }
            }
            #pragma unroll
            for (int u = 0; u < TPW; u++) {
                d0[u] += __shfl_xor_sync(0xffffffffu, d0[u], 1);
                d0[u] += __shfl_xor_sync(0xffffffffu, d0[u], 2);
                d1[u] += __shfl_xor_sync(0xffffffffu, d1[u], 1);
                d1[u] += __shfl_xor_sync(0xffffffffu, d1[u], 2);
                logq0[u] -= dt * (csum - d0[u]);
                logq1[u] -= dt * (csum - d1[u]);
            }

            __syncwarp();

            // GEMM2 for both tiles
            float v[TPW][2][4];
            #pragma unroll
            for (int u = 0; u < TPW; u++) {
                float2 bb0 = *(const float2*)&sb2s[2 * tg];
                float2 bb1 = *(const float2*)&sb2s[8 + 2 * tg];
                float va0[4] = {bb0.x, bb0.y, bb0.x, bb0.y};
                float vb0[4] = {0.f, 0.f, 0.f, 0.f};
                float va1[4] = {bb1.x, bb1.y, bb1.x, bb1.y};
                float vb1[4] = {0.f, 0.f, 0.f, 0.f};
                #pragma unroll
                for (int kt = 0; kt < 8; kt++) {
                    uint4 hv = *(const uint4*)&buf[u][kt * 128 + ldb];
                    uint32_t ha[4] = {hv.x, hv.y, hv.z, hv.w};
                    if (kt < 4) {
                        mma_tf32(va0, ha, w2f[kt][0][0], w2f[kt][0][1]);
                        mma_tf32(va1, ha, w2f[kt][1][0], w2f[kt][1][1]);
                    } else {
                        mma_tf32(vb0, ha, w2f[kt][0][0], w2f[kt][0][1]);
                        mma_tf32(vb1, ha, w2f[kt][1][0], w2f[kt][1][1]);
                    }
                }
                #pragma unroll
                for (int i = 0; i < 4; i++) {
                    v[u][0][i] = va0[i] + vb0[i];
                    v[u][1][i] = va1[i] + vb1[i];
                }
            }
            __syncwarp();

            // v relayout via shuffles + exact x update, both tiles
            #pragma unroll
            for (int u = 0; u < TPW; u++)
                #pragma unroll
                for (int kt = 0; kt < 2; kt++) {
                    int src0 = gb | (tg >> 1);
                    int src1 = gb | (2 + (tg >> 1));
                    float e00 = __shfl_sync(0xffffffffu, v[u][kt][0], src0);
                    float e01 = __shfl_sync(0xffffffffu, v[u][kt][1], src0);
                    float e10 = __shfl_sync(0xffffffffu, v[u][kt][2], src0);
                    float e11 = __shfl_sync(0xffffffffu, v[u][kt][3], src0);
                    float f00 = __shfl_sync(0xffffffffu, v[u][kt][0], src1);
                    float f01 = __shfl_sync(0xffffffffu, v[u][kt][1], src1);
                    float f10 = __shfl_sync(0xffffffffu, v[u][kt][2], src1);
                    float f11 = __shfl_sync(0xffffffffu, v[u][kt][3], src1);
                    bool odd = (tg & 1);
                    xe[u][kt][0] = fmaf(dt, odd ? e01 : e00, xe[u][kt][0]);
                    xe[u][kt][1] = fmaf(dt, odd ? e11 : e10, xe[u][kt][1]);
                    xe[u][kt][2] = fmaf(dt, odd ? f01 : f00, xe[u][kt][2]);
                    xe[u][kt][3] = fmaf(dt, odd ? f11 : f10, xe[u][kt][3]);
                }
        }

        // output, both tiles
        #pragma unroll
        for (int u = 0; u < TPW; u++) {
            #pragma unroll
            for (int kt = 0; kt < 2; kt++) {
                out[(size_t)(row0[u] + g)     * 16 + 8 * kt + tg]     = xe[u][kt][0];
                out[(size_t)(row0[u] + g + 8) * 16 + 8 * kt + tg]     = xe[u][kt][1];
                out[(size_t)(row0[u] + g)     * 16 + 8 * kt + tg + 4] = xe[u][kt][2];
                out[(size_t)(row0[u] + g + 8) * 16 + 8 * kt + tg + 4] = xe[u][kt][3];
            }
            if (tg == 0) {
                out[(size_t)batch * 16 + row0[u] + g]     = logq0[u];
                out[(size_t)batch * 16 + row0[u] + g + 8] = logq1[u];
            }
        }
    }
}

extern "C" void kernel_launch(void* const* d_in, const int* in_sizes, int n_in,
                              void* d_out, int out_size) {
    const float* x0 = (const float*)d_in[0];
    const float* W1 = (const float*)d_in[1];
    const float* b1 = (const float*)d_in[2];
    const float* W2 = (const float*)d_in[3];
    const float* b2 = (const float*)d_in[4];
    float* out = (float*)d_out;

    const int batch = in_sizes[0] / 16;   // 131072, divisible by 32
    flow_kernel<<<GRID, THREADS>>>(x0, W1, b1, W2, b2, out, batch);
}

// round 15
// speedup vs baseline: 1.8285x; 1.4276x over previous
#include <cuda_runtime.h>
#include <math.h>
#include <stdint.h>

// Flow_49546742727298: CNF Euler, exact divergence via analytic trace.
// R15: fp16 m16n8k16 MMA. Fragment-layout alignment eliminates ALL relayout:
//   GEMM1 C-frag (h) == GEMM2 A-frag coords (pack-only); GEMM2 C-frag (v) ==
//   x A-frag coords (direct FMA update). No smem h-buffer, no shuffles, no
//   syncwarp in the hot loop. Persistent warps, 3 CTAs/SM.

#define THREADS 128
#define NSTEPS  2
#define GRID    (3 * 148)

__device__ __forceinline__ uint32_t pack_f16x2(float lo, float hi) {
    uint32_t d; asm("cvt.rn.f16x2.f32 %0, %1, %2;" : "=r"(d) : "f"(hi), "f"(lo)); return d;
}
__device__ __forceinline__ float fast_tanh(float x) {
    float y; asm("tanh.approx.f32 %0, %1;" : "=f"(y) : "f"(x)); return y;
}
// D = A(16x16 f16) @ B(16x8 f16) + C, fp32 accumulate.
__device__ __forceinline__ void mma_f16(float c[4], const uint32_t a[4],
                                        const uint32_t b0, const uint32_t b1) {
    asm("mma.sync.aligned.m16n8k16.row.col.f32.f16.f16.f32 "
        "{%0,%1,%2,%3}, {%4,%5,%6,%7}, {%8,%9}, {%0,%1,%2,%3};"
        : "+f"(c[0]), "+f"(c[1]), "+f"(c[2]), "+f"(c[3])
        : "r"(a[0]), "r"(a[1]), "r"(a[2]), "r"(a[3]), "r"(b0), "r"(b1));
}

__global__ void __launch_bounds__(THREADS, 3)
flow_kernel(const float* __restrict__ x0,
            const float* __restrict__ W1,
            const float* __restrict__ b1,
            const float* __restrict__ W2,
            const float* __restrict__ b2,
            float* __restrict__ out,
            int batch)
{
    __shared__ float sbias[2][64];   // [s][j]: b1[j] + t_s*wt[j]
    __shared__ float scj[64];        // c_j
    __shared__ __align__(8) float sb2s[16];

    const int tid  = threadIdx.x;
    const int lane = tid & 31;
    const int warp = tid >> 5;
    const int g    = lane >> 2;   // row-within-8
    const int tg   = lane & 3;    // thread-in-group

    // ---- per-CTA tables ----
    if (tid < 64) {
        const int j = tid;
        float c = 0.f;
        #pragma unroll
        for (int i = 0; i < 16; i++)
            c += W1[i * 64 + j] * W2[j * 16 + i];
        float bb = b1[j];
        float wt = W1[16 * 64 + j];
        scj[j] = c;
        sbias[0][j] = bb;
        sbias[1][j] = fmaf(0.5f, wt, bb);
    } else if (tid < 80) {
        sb2s[tid - 64] = b2[tid - 64];
    }
    __syncthreads();

    float csum;
    {
        float cpart = scj[lane] + scj[lane + 32];
        #pragma unroll
        for (int d = 16; d >= 1; d >>= 1)
            cpart += __shfl_xor_sync(0xffffffffu, cpart, d);
        csum = cpart;
    }

    // c_j at this thread's C columns (8nt+2tg, +1)
    float cja[8], cjb[8];
    #pragma unroll
    for (int nt = 0; nt < 8; nt++) {
        float2 cc = *(const float2*)&scj[8 * nt + 2 * tg];
        cja[nt] = cc.x; cjb[nt] = cc.y;
    }

    // ---- persistent fp16 weight B-fragments ----
    // W1 (k=16 x n=64): w1f[nt] = { pack(W1[2tg][8nt+g],   W1[2tg+1][8nt+g]),
    //                              pack(W1[2tg+8][8nt+g], W1[2tg+9][8nt+g]) }
    uint32_t w1f[8][2];
    #pragma unroll
    for (int nt = 0; nt < 8; nt++) {
        int col = 8 * nt + g;
        w1f[nt][0] = pack_f16x2(W1[(2 * tg)     * 64 + col], W1[(2 * tg + 1) * 64 + col]);
        w1f[nt][1] = pack_f16x2(W1[(2 * tg + 8) * 64 + col], W1[(2 * tg + 9) * 64 + col]);
    }
    // W2 (k=64 x n=16): kt = 0..3 (16 k each), nt = 0..1
    uint32_t w2f[4][2][2];
    #pragma unroll
    for (int kt = 0; kt < 4; kt++)
        #pragma unroll
        for (int nt = 0; nt < 2; nt++) {
            int col = 8 * nt + g;
            int k0 = 16 * kt + 2 * tg;
            w2f[kt][nt][0] = pack_f16x2(W2[k0       * 16 + col], W2[(k0 + 1) * 16 + col]);
            w2f[kt][nt][1] = pack_f16x2(W2[(k0 + 8) * 16 + col], W2[(k0 + 9) * 16 + col]);
        }

    const float dt = 0.5f;
    const int gwarp  = blockIdx.x * 4 + warp;
    const int nwarps = GRID * 4;
    const int ntiles = batch >> 4;

    for (int wt = gwarp; wt < ntiles; wt += nwarps) {
        const int row0 = wt << 4;

        // x in v-C-frag == A-frag coordinates: xe[nt][0..3] =
        //   (g, 8nt+2tg), (g, 8nt+2tg+1), (g+8, 8nt+2tg), (g+8, 8nt+2tg+1)
        float xe[2][4];
        #pragma unroll
        for (int nt = 0; nt < 2; nt++) {
            float2 lo = *(const float2*)&x0[(size_t)(row0 + g)     * 16 + 8 * nt + 2 * tg];
            float2 hi = *(const float2*)&x0[(size_t)(row0 + g + 8) * 16 + 8 * nt + 2 * tg];
            xe[nt][0] = lo.x; xe[nt][1] = lo.y;
            xe[nt][2] = hi.x; xe[nt][3] = hi.y;
        }

        float logq0 = 0.f, logq1 = 0.f;

        #pragma unroll
        for (int s = 0; s < NSTEPS; s++) {
            // x A-frag: a0=(g, 2tg..), a1=(g+8, 2tg..), a2=(g, 2tg+8..), a3=(g+8, 2tg+8..)
            uint32_t xa[4];
            xa[0] = pack_f16x2(xe[0][0], xe[0][1]);
            xa[1] = pack_f16x2(xe[0][2], xe[0][3]);
            xa[2] = pack_f16x2(xe[1][0], xe[1][1]);
            xa[3] = pack_f16x2(xe[1][2], xe[1][3]);

            // GEMM1: h = x @ W1 + bse  (one MMA per nt, K=16 covers all of x)
            float h[8][4];
            #pragma unroll
            for (int nt = 0; nt < 8; nt++) {
                float2 bb = *(const float2*)&sbias[s][8 * nt + 2 * tg];
                h[nt][0] = bb.x; h[nt][1] = bb.y;
                h[nt][2] = bb.x; h[nt][3] = bb.y;
                mma_f16(h[nt], xa, w1f[nt][0], w1f[nt][1]);
            }

            // tanh + divergence partials
            float d0 = 0.f, d1 = 0.f;
            #pragma unroll
            for (int nt = 0; nt < 8; nt++) {
                h[nt][0] = fast_tanh(h[nt][0]);
                h[nt][1] = fast_tanh(h[nt][1]);
                h[nt][2] = fast_tanh(h[nt][2]);
                h[nt][3] = fast_tanh(h[nt][3]);
                d0 = fmaf(h[nt][0] * h[nt][0], cja[nt], d0);
                d0 = fmaf(h[nt][1] * h[nt][1], cjb[nt], d0);
                d1 = fmaf(h[nt][2] * h[nt][2], cja[nt], d1);
                d1 = fmaf(h[nt][3] * h[nt][3], cjb[nt], d1);
            }
            d0 += __shfl_xor_sync(0xffffffffu, d0, 1);
            d0 += __shfl_xor_sync(0xffffffffu, d0, 2);
            d1 += __shfl_xor_sync(0xffffffffu, d1, 1);
            d1 += __shfl_xor_sync(0xffffffffu, d1, 2);
            logq0 -= dt * (csum - d0);
            logq1 -= dt * (csum - d1);

            // h C-frags -> GEMM2 A-frags: pure pack, no data movement.
            // A-frag(kt) rows g,g+8, cols 16kt+2tg(+1) and +8 = C-frags nt=2kt, 2kt+1.
            uint32_t ha[4][4];
            #pragma unroll
            for (int kt = 0; kt < 4; kt++) {
                ha[kt][0] = pack_f16x2(h[2 * kt][0],     h[2 * kt][1]);
                ha[kt][1] = pack_f16x2(h[2 * kt][2],     h[2 * kt][3]);
                ha[kt][2] = pack_f16x2(h[2 * kt + 1][0], h[2 * kt + 1][1]);
                ha[kt][3] = pack_f16x2(h[2 * kt + 1][2], h[2 * kt + 1][3]);
            }

            // GEMM2: v = h @ W2 + b2 (two 2-deep chains per nt)
            float v[2][4];
            #pragma unroll
            for (int nt = 0; nt < 2; nt++) {
                float2 bb = *(const float2*)&sb2s[8 * nt + 2 * tg];
                float va[4] = {bb.x, bb.y, bb.x, bb.y};
                float vb[4] = {0.f, 0.f, 0.f, 0.f};
                mma_f16(va, ha[0], w2f[0][nt][0], w2f[0][nt][1]);
                mma_f16(vb, ha[1], w2f[1][nt][0], w2f[1][nt][1]);
                mma_f16(va, ha[2], w2f[2][nt][0], w2f[2][nt][1]);
                mma_f16(vb, ha[3], w2f[3][nt][0], w2f[3][nt][1]);
                #pragma unroll
                for (int i = 0; i < 4; i++) v[nt][i] = va[i] + vb[i];
            }

            // v C-frag layout == xe layout: direct exact-fp32 update.
            #pragma unroll
            for (int nt = 0; nt < 2; nt++)
                #pragma unroll
                for (int i = 0; i < 4; i++)
                    xe[nt][i] = fmaf(dt, v[nt][i], xe[nt][i]);
        }

        // output (float2 stores; layout matches input)
        #pragma unroll
        for (int nt = 0; nt < 2; nt++) {
            *(float2*)&out[(size_t)(row0 + g)     * 16 + 8 * nt + 2 * tg] =
                make_float2(xe[nt][0], xe[nt][1]);
            *(float2*)&out[(size_t)(row0 + g + 8) * 16 + 8 * nt + 2 * tg] =
                make_float2(xe[nt][2], xe[nt][3]);
        }
        if (tg == 0) {
            out[(size_t)batch * 16 + row0 + g]     = logq0;
            out[(size_t)batch * 16 + row0 + g + 8] = logq1;
        }
    }
}

extern "C" void kernel_launch(void* const* d_in, const int* in_sizes, int n_in,
                              void* d_out, int out_size) {
    const float* x0 = (const float*)d_in[0];
    const float* W1 = (const float*)d_in[1];
    const float* b1 = (const float*)d_in[2];
    const float* W2 = (const float*)d_in[3];
    const float* b2 = (const float*)d_in[4];
    float* out = (float*)d_out;

    const int batch = in_sizes[0] / 16;
    flow_kernel<<<GRID, THREADS>>>(x0, W1, b1, W2, b2, out, batch);
}